// round 15
// baseline (speedup 1.0000x reference)
#include <cuda_runtime.h>
#include <cuda_bf16.h>
#include <cstdint>
#include <math.h>

// Problem dims (fixed)
#define NB   8
#define NS   1024
#define NH   16
#define NDK  64
#define FDEC 1024
#define FD   16
#define KINR 784
#define KP   1024
#define MROWS (NB*NS)   // 8192

// ---------------- scratch (static __device__, no allocation) ----------------
__device__ float g_xcat[MROWS * KP];     // concat input, tf32-rounded
__device__ float g_x   [MROWS * FDEC];   // dense output (residual, fp32)
__device__ float g_xn  [MROWS * FDEC];   // LN output, tf32-rounded
__device__ float g_q   [MROWS * FDEC];   // tf32-rounded
__device__ float g_k   [MROWS * FDEC];   // tf32-rounded
__device__ float g_v   [MROWS * FDEC];   // tf32-rounded
__device__ float g_o   [MROWS * FDEC];   // attention out, fp32
__device__ float g_wd  [FDEC * KP];
__device__ float g_wqr [FDEC * KP];
__device__ float g_wkr [FDEC * KP];
__device__ float g_wvr [FDEC * KP];
__device__ float g_wc  [FD * FDEC];      // dcw @ wo
__device__ float g_cadd[FD];             // dcw . bo + dec_b

// ---------------- PTX helpers ------------------------------------------------
__device__ __forceinline__ uint32_t smem_u32(const void* p) {
    uint32_t a;
    asm("{ .reg .u64 t; cvta.to.shared.u64 t, %1; cvt.u32.u64 %0, t; }" : "=r"(a) : "l"(p));
    return a;
}

#define LDSM4(R, A) \
    asm volatile("ldmatrix.sync.aligned.m8n8.x4.shared.b16 {%0,%1,%2,%3}, [%4];" \
        : "=r"((R)[0]), "=r"((R)[1]), "=r"((R)[2]), "=r"((R)[3]) : "r"(A))

#define MMA_TF32(C, A, B0, B1) \
    asm volatile("mma.sync.aligned.m16n8k8.row.col.f32.tf32.tf32.f32 " \
        "{%0,%1,%2,%3},{%4,%5,%6,%7},{%8,%9},{%0,%1,%2,%3};" \
        : "+f"((C)[0]), "+f"((C)[1]), "+f"((C)[2]), "+f"((C)[3]) \
        : "r"((A)[0]), "r"((A)[1]), "r"((A)[2]), "r"((A)[3]), "r"(B0), "r"(B1))

__device__ __forceinline__ uint32_t to_tf32(float f) {
    uint32_t r;
    asm("cvt.rna.tf32.f32 %0, %1;" : "=r"(r) : "f"(f));
    return r;
}
__device__ __forceinline__ float tf32r(float f) {
    return __uint_as_float(to_tf32(f));
}

__device__ __forceinline__ void cpa16(uint32_t dst, const void* src) {
    asm volatile("cp.async.cg.shared.global [%0], [%1], 16;" :: "r"(dst), "l"(src));
}
#define CP_COMMIT() asm volatile("cp.async.commit_group;" ::: "memory")
#define CP_WAIT(n)  asm volatile("cp.async.wait_group %0;" :: "n"(n) : "memory")

// ---------------- producers (tf32-rounded outputs) ---------------------------
__global__ void __launch_bounds__(256) concat_k(
    const float* __restrict__ r, const float* __restrict__ z,
    float* __restrict__ xcat)
{
    int idx = blockIdx.x * 256 + threadIdx.x;
    if (idx >= MROWS * KP) return;
    int m = idx >> 10, f = idx & 1023;
    float v = (f < 16) ? r[m * 16 + f]
            : (f < KINR) ? z[(m >> 10) * 768 + (f - 16)] : 0.f;
    xcat[idx] = tf32r(v);
}

__global__ void __launch_bounds__(256) roundpad_k(
    const float* __restrict__ w, int Ksrc, float* __restrict__ dst)
{
    int idx = blockIdx.x * 256 + threadIdx.x;
    if (idx >= FDEC * KP) return;
    int n = idx >> 10, k = idx & 1023;
    dst[idx] = (k < Ksrc) ? tf32r(w[n * Ksrc + k]) : 0.f;
}

// wc[n][c] = sum_j dcw[n][j] * wo[j][c]   (16 x 1024), exact fp32
__global__ void __launch_bounds__(256) wcomb_k(
    const float* __restrict__ dcw, const float* __restrict__ wo,
    float* __restrict__ wc)
{
    const int n = threadIdx.x >> 4;
    const int c = blockIdx.x * 16 + (threadIdx.x & 15);
    const float* dr = dcw + n * FDEC;
    float acc = 0.f;
    #pragma unroll 8
    for (int j = 0; j < FDEC; j++)
        acc += dr[j] * wo[(size_t)j * FDEC + c];
    wc[n * FDEC + c] = acc;
}

__global__ void __launch_bounds__(512) cvec_k(
    const float* __restrict__ dcw, const float* __restrict__ bo,
    const float* __restrict__ dcb, float* __restrict__ cadd)
{
    const int n = threadIdx.x >> 5, lane = threadIdx.x & 31;
    float sum = 0.f;
    #pragma unroll
    for (int i = 0; i < 8; i++) {
        float4 a = ((const float4*)(dcw + n * FDEC))[lane + i * 32];
        float4 b = ((const float4*)bo)[lane + i * 32];
        sum += a.x * b.x + a.y * b.y + a.z * b.z + a.w * b.w;
    }
    #pragma unroll
    for (int o = 16; o; o >>= 1) sum += __shfl_xor_sync(0xffffffffu, sum, o);
    if (lane == 0) cadd[n] = sum + dcb[n];
}

// ---------------- LayerNorm (fp32 in, tf32-rounded out) ----------------------
__device__ __forceinline__ float blockReduce(float val, float* sh)
{
    __syncthreads();
    int lane = threadIdx.x & 31, wid = threadIdx.x >> 5;
    #pragma unroll
    for (int o = 16; o; o >>= 1) val += __shfl_xor_sync(0xffffffffu, val, o);
    if (lane == 0) sh[wid] = val;
    __syncthreads();
    if (wid == 0) {
        val = (lane < 8) ? sh[lane] : 0.f;
        #pragma unroll
        for (int o = 4; o; o >>= 1) val += __shfl_xor_sync(0xffffffffu, val, o);
        if (lane == 0) sh[0] = val;
    }
    __syncthreads();
    return sh[0];
}

__global__ void __launch_bounds__(256) ln_k(
    const float* __restrict__ x, const float* __restrict__ g,
    const float* __restrict__ beta, float* __restrict__ xn)
{
    __shared__ float red[32];
    int row = blockIdx.x;
    float4 v = ((const float4*)(x + (size_t)row * 1024))[threadIdx.x];
    float s = blockReduce(v.x + v.y + v.z + v.w, red);
    float mean = s * (1.0f / 1024.0f);
    float dx = v.x - mean, dy = v.y - mean, dz = v.z - mean, dw = v.w - mean;
    float s2 = blockReduce(dx*dx + dy*dy + dz*dz + dw*dw, red);
    float inv = rsqrtf(s2 * (1.0f / 1024.0f) + 1e-6f);
    float4 gg = ((const float4*)g)[threadIdx.x];
    float4 bb = ((const float4*)beta)[threadIdx.x];
    float4 o;
    o.x = tf32r(gg.x * dx * inv + bb.x);
    o.y = tf32r(gg.y * dy * inv + bb.y);
    o.z = tf32r(gg.z * dz * inv + bb.z);
    o.w = tf32r(gg.w * dw * inv + bb.w);
    ((float4*)(xn + (size_t)row * 1024))[threadIdx.x] = o;
}

// ---------------- tf32 mma GEMM with ldmatrix fragments ----------------------
#define GSTR  36
#define TILE_BYTES (128 * GSTR * 4)
#define STAGE_B (2 * TILE_BYTES)
#define GEMM_SMEM (3 * STAGE_B)

template<int MODE>
__global__ void __launch_bounds__(256) gemm_tf32(
    const float* __restrict__ A, const float* __restrict__ Bw,
    const float* __restrict__ bias, float* __restrict__ C)
{
    extern __shared__ char sm[];
    const uint32_t sbase = smem_u32(sm);
    const int tid = threadIdx.x, lane = tid & 31, wid = tid >> 5;
    const int g4 = lane >> 2, t4 = lane & 3;
    const int bm = blockIdx.y * 128, bn = blockIdx.x * 128;
    const int wm = (wid & 3) * 32, wn = (wid >> 2) * 64;

    float acc[2][8][4];
    #pragma unroll
    for (int a = 0; a < 2; a++)
        #pragma unroll
        for (int b = 0; b < 8; b++)
            #pragma unroll
            for (int c = 0; c < 4; c++) acc[a][b][c] = 0.f;

    const uint32_t aoff =
        ((uint32_t)(wm + (lane & 7) + ((lane >> 3) & 1) * 8) * GSTR
         + ((lane >> 4) << 2)) * 4;
    const uint32_t boff =
        ((uint32_t)(wn + (lane & 7)) * GSTR + ((lane >> 3) & 3) * 4) * 4;

    auto load_stage = [&](int slot, int k0) {
        const uint32_t sa = sbase + slot * STAGE_B;
        #pragma unroll
        for (int c = 0; c < 4; c++) {
            int chunk = tid + c * 256;
            int row = chunk >> 3, seg = chunk & 7;
            cpa16(sa + row * (GSTR*4) + seg * 16,
                  A + (size_t)(bm + row) * KP + k0 + seg * 4);
        }
        const uint32_t sb = sa + TILE_BYTES;
        #pragma unroll
        for (int c = 0; c < 4; c++) {
            int chunk = tid + c * 256;
            int row = chunk >> 3, seg = chunk & 7;
            cpa16(sb + row * (GSTR*4) + seg * 16,
                  Bw + (size_t)(bn + row) * KP + k0 + seg * 4);
        }
    };

    load_stage(0, 0);  CP_COMMIT();
    load_stage(1, 32); CP_COMMIT();

    for (int i = 0; i < 32; i++) {
        if (i < 31) { CP_WAIT(1); } else { CP_WAIT(0); }
        __syncthreads();
        if (i + 2 < 32) { load_stage((i + 2) % 3, (i + 2) * 32); CP_COMMIT(); }

        const uint32_t As = sbase + (i % 3) * STAGE_B;
        const uint32_t Bs = As + TILE_BYTES;

        uint32_t a[4][2][4];
        #pragma unroll
        for (int kk = 0; kk < 4; kk++)
            #pragma unroll
            for (int am = 0; am < 2; am++)
                LDSM4(a[kk][am], As + aoff + am * (16 * GSTR * 4) + kk * 32);

        #pragma unroll
        for (int nt = 0; nt < 8; nt++) {
            uint32_t b01[4], b23[4];
            const uint32_t bb = Bs + boff + nt * (8 * GSTR * 4);
            LDSM4(b01, bb);
            LDSM4(b23, bb + 64);
            MMA_TF32(acc[0][nt], a[0][0], b01[0], b01[1]);
            MMA_TF32(acc[1][nt], a[0][1], b01[0], b01[1]);
            MMA_TF32(acc[0][nt], a[1][0], b01[2], b01[3]);
            MMA_TF32(acc[1][nt], a[1][1], b01[2], b01[3]);
            MMA_TF32(acc[0][nt], a[2][0], b23[0], b23[1]);
            MMA_TF32(acc[1][nt], a[2][1], b23[0], b23[1]);
            MMA_TF32(acc[0][nt], a[3][0], b23[2], b23[3]);
            MMA_TF32(acc[1][nt], a[3][1], b23[2], b23[3]);
        }
    }

    #pragma unroll
    for (int am = 0; am < 2; am++) {
        #pragma unroll
        for (int nt = 0; nt < 8; nt++) {
            int mrow = bm + wm + am * 16 + g4;
            int ncol = bn + wn + nt * 8 + t4 * 2;
            float b0 = bias[ncol], b1 = bias[ncol + 1];
            #pragma unroll
            for (int r = 0; r < 2; r++) {
                int m = mrow + r * 8;
                float v0 = acc[am][nt][r * 2]     + b0;
                float v1 = acc[am][nt][r * 2 + 1] + b1;
                if (MODE == 0) {
                    *(float2*)&C[(size_t)m * 1024 + ncol] = make_float2(v0, v1);
                } else {
                    int bb = m >> 10, s = m & 1023, h = ncol >> 6, d = ncol & 63;
                    *(float2*)&C[(size_t)(((bb << 4) + h) * 1024 + s) * 64 + d] =
                        make_float2(tf32r(v0), tf32r(v1));
                }
            }
        }
    }
}

// ---------------- fused decode: out = x.dw + o.wc + cadd, transposed ---------
__global__ void __launch_bounds__(512) dec2_k(
    const float* __restrict__ x, const float* __restrict__ o,
    const float* __restrict__ dw, const float* __restrict__ wc,
    const float* __restrict__ cadd, float* __restrict__ out)
{
    const int m = blockIdx.x;
    const int b = m >> 10, s = m & 1023;
    const int n = threadIdx.x >> 5;
    const int lane = threadIdx.x & 31;
    const float4* xr = (const float4*)(x  + (size_t)m * FDEC);
    const float4* orr = (const float4*)(o + (size_t)m * FDEC);
    const float4* wr = (const float4*)(dw + (size_t)n * FDEC);
    const float4* cr = (const float4*)(wc + (size_t)n * FDEC);
    float sum = 0.f;
    #pragma unroll
    for (int i = 0; i < 8; i++) {
        float4 a = xr[lane + i * 32];
        float4 w = wr[lane + i * 32];
        float4 oo = orr[lane + i * 32];
        float4 c = cr[lane + i * 32];
        sum += a.x * w.x + a.y * w.y + a.z * w.z + a.w * w.w;
        sum += oo.x * c.x + oo.y * c.y + oo.z * c.z + oo.w * c.w;
    }
    #pragma unroll
    for (int oo = 16; oo; oo >>= 1) sum += __shfl_xor_sync(0xffffffffu, sum, oo);
    if (lane == 0)
        out[(size_t)(b * FD + n) * NS + s] = sum + cadd[n];
}

// ---------------- tf32 mma flash attention, ALiBi folded into mma ------------
// Q/K augmented to 72 dims: Q[64]=slope_hi, Q[65]=slope_lo; K[64]=K[65]=jg.
// S mma then yields 0.125*q.k + slope*jg exactly enough (two-term slope split).
// Q/K stride 76 floats; V/P stride 68. Per-element softmax has no bias math;
// mask only on diagonal tiles. P stored as float2 pairs.
#define ASTR 68
#define QSTR 76
#define ATTN_SMEM (((128 + 64) * QSTR + (64 + 128) * ASTR) * (int)sizeof(float)) // 110592

__global__ void __launch_bounds__(256) attn_tc(
    const float* __restrict__ q, const float* __restrict__ k,
    const float* __restrict__ v, float* __restrict__ o)
{
    extern __shared__ float smf[];
    float* Qs = smf;                   // [128][76] scaled Q + slope cols
    float* Ks = Qs + 128 * QSTR;       // [64][76]  K[j][d] + jg cols
    float* Vs = Ks + 64 * QSTR;        // [64][68]  V^T: Vs[d][j]
    float* Ps = Vs + 64 * ASTR;        // [128][68] P, tf32-rounded

    const int qc = blockIdx.x, h = blockIdx.y, b = blockIdx.z;
    const int tid = threadIdx.x, lane = tid & 31, w = tid >> 5;
    const int g4 = lane >> 2, t4 = lane & 3;

    const uint32_t sQs = smem_u32(Qs), sKs = smem_u32(Ks);
    const uint32_t sVs = smem_u32(Vs), sPs = smem_u32(Ps);

    const size_t head = (size_t)(b * NH + h) * NS * NDK;
    const float* qb = q + head;
    const float* kb = k + head;
    const float* vb = v + head;

    const float slope = exp2f(-0.5f * (float)(h + 1));
    const float slope_hi = tf32r(slope);
    const float slope_lo = tf32r(slope - slope_hi);

    // load Q chunk (128 rows), scaled; fill slope cols
    {
        const int row = tid >> 1, col0 = (tid & 1) * 32;
        const float* src = qb + (size_t)(qc * 128 + row) * 64 + col0;
        float* dst = Qs + row * QSTR + col0;
        #pragma unroll
        for (int c = 0; c < 32; c += 4) {
            float4 t = *(const float4*)(src + c);
            t.x *= 0.125f; t.y *= 0.125f; t.z *= 0.125f; t.w *= 0.125f;
            *(float4*)(dst + c) = t;
        }
        if ((tid & 1) == 0) {
            float* e = Qs + row * QSTR + 64;
            e[0] = slope_hi; e[1] = slope_lo;
            e[2] = 0.f; e[3] = 0.f; e[4] = 0.f; e[5] = 0.f; e[6] = 0.f; e[7] = 0.f;
        }
    }

    // fragment offsets
    const uint32_t bfragK = ((uint32_t)(lane & 7) * QSTR + ((lane >> 3) & 3) * 4) * 4;
    const uint32_t bfragV = ((uint32_t)(lane & 7) * ASTR + ((lane >> 3) & 3) * 4) * 4;
    const uint32_t afragQ =
        ((uint32_t)(w * 16 + (lane & 7) + ((lane >> 3) & 1) * 8) * QSTR
         + ((lane >> 4) << 2)) * 4;
    const uint32_t afragP =
        ((uint32_t)(w * 16 + (lane & 7) + ((lane >> 3) & 1) * 8) * ASTR
         + ((lane >> 4) << 2)) * 4;

    float oacc[8][4];
    #pragma unroll
    for (int dt = 0; dt < 8; dt++)
        #pragma unroll
        for (int c = 0; c < 4; c++) oacc[dt][c] = 0.f;
    float mrow[2] = { -1e30f, -1e30f };
    float lrow[2] = { 0.f, 0.f };

    const int lrow_ld = tid >> 2, lcol0 = (tid & 3) * 16;
    const int kmax = 2 * qc + 1;

    __syncthreads();   // Qs ready

    for (int kc = 0; kc <= kmax; kc++) {
        // load K [j][d] (+ jg cols); V transposed [d][j]
        {
            const float* ksrc = kb + (size_t)(kc * 64 + lrow_ld) * 64 + lcol0;
            const float* vsrc = vb + (size_t)(kc * 64 + lrow_ld) * 64 + lcol0;
            float* kd = Ks + lrow_ld * QSTR + lcol0;
            #pragma unroll
            for (int c = 0; c < 16; c += 4) {
                float4 t = *(const float4*)(ksrc + c);
                *(float4*)(kd + c) = t;
                float4 tv = *(const float4*)(vsrc + c);
                Vs[(lcol0 + c + 0) * ASTR + lrow_ld] = tv.x;
                Vs[(lcol0 + c + 1) * ASTR + lrow_ld] = tv.y;
                Vs[(lcol0 + c + 2) * ASTR + lrow_ld] = tv.z;
                Vs[(lcol0 + c + 3) * ASTR + lrow_ld] = tv.w;
            }
            if ((tid & 3) == 0) {
                float jg = (float)(kc * 64 + lrow_ld);
                float* e = Ks + lrow_ld * QSTR + 64;
                e[0] = jg; e[1] = jg;
                e[2] = 0.f; e[3] = 0.f; e[4] = 0.f; e[5] = 0.f; e[6] = 0.f; e[7] = 0.f;
            }
        }
        __syncthreads();

        const bool active = !(kc == kmax && w < 4);
        if (active) {
            // Q a-fragments (9 kk tiles incl. slope cols)
            uint32_t qa[9][4];
            #pragma unroll
            for (int kk = 0; kk < 9; kk++)
                LDSM4(qa[kk], sQs + afragQ + kk * 32);

            // S = [Q|slope] [K|jg]^T
            float sc[8][4];
            #pragma unroll
            for (int nt = 0; nt < 8; nt++) {
                sc[nt][0] = sc[nt][1] = sc[nt][2] = sc[nt][3] = 0.f;
                const uint32_t kb_ = sKs + bfragK + nt * (8 * QSTR * 4);
                uint32_t b0[4], b1[4], b2[4], b3[4], b4[4];
                LDSM4(b0, kb_);
                LDSM4(b1, kb_ + 64);
                LDSM4(b2, kb_ + 128);
                LDSM4(b3, kb_ + 192);
                LDSM4(b4, kb_ + 256);          // cols 64-79; use first 2 regs
                MMA_TF32(sc[nt], qa[0], b0[0], b0[1]);
                MMA_TF32(sc[nt], qa[1], b0[2], b0[3]);
                MMA_TF32(sc[nt], qa[2], b1[0], b1[1]);
                MMA_TF32(sc[nt], qa[3], b1[2], b1[3]);
                MMA_TF32(sc[nt], qa[4], b2[0], b2[1]);
                MMA_TF32(sc[nt], qa[5], b2[2], b2[3]);
                MMA_TF32(sc[nt], qa[6], b3[0], b3[1]);
                MMA_TF32(sc[nt], qa[7], b3[2], b3[3]);
                MMA_TF32(sc[nt], qa[8], b4[0], b4[1]);
            }

            // softmax (bias already in sc); mask only on diagonal tiles
            const bool diag = (kc >= 2 * qc);
            #pragma unroll
            for (int half = 0; half < 2; half++) {
                const int wr = w * 16 + g4 + half * 8;
                const int ig = qc * 128 + wr;
                float mx = -1e30f;
                if (diag) {
                    #pragma unroll
                    for (int nt = 0; nt < 8; nt++) {
                        #pragma unroll
                        for (int e = 0; e < 2; e++) {
                            int jg = kc * 64 + nt * 8 + t4 * 2 + e;
                            float val = sc[nt][half * 2 + e];
                            if (jg > ig) val -= 1e9f;
                            sc[nt][half * 2 + e] = val;
                            mx = fmaxf(mx, val);
                        }
                    }
                } else {
                    #pragma unroll
                    for (int nt = 0; nt < 8; nt++) {
                        mx = fmaxf(mx, fmaxf(sc[nt][half * 2], sc[nt][half * 2 + 1]));
                    }
                }
                mx = fmaxf(mx, __shfl_xor_sync(0xffffffffu, mx, 1));
                mx = fmaxf(mx, __shfl_xor_sync(0xffffffffu, mx, 2));
                float mnew = fmaxf(mrow[half], mx);
                float corr = __expf(mrow[half] - mnew);
                mrow[half] = mnew;
                float rs = 0.f;
                #pragma unroll
                for (int nt = 0; nt < 8; nt++) {
                    float p0 = __expf(sc[nt][half * 2]     - mnew);
                    float p1 = __expf(sc[nt][half * 2 + 1] - mnew);
                    rs += p0 + p1;
                    *(float2*)&Ps[wr * ASTR + nt * 8 + t4 * 2] =
                        make_float2(tf32r(p0), tf32r(p1));
                }
                rs += __shfl_xor_sync(0xffffffffu, rs, 1);
                rs += __shfl_xor_sync(0xffffffffu, rs, 2);
                lrow[half] = lrow[half] * corr + rs;
                #pragma unroll
                for (int dt = 0; dt < 8; dt++) {
                    oacc[dt][half * 2]     *= corr;
                    oacc[dt][half * 2 + 1] *= corr;
                }
            }
            __syncwarp();

            // O += P V
            uint32_t pa[8][4];
            #pragma unroll
            for (int kk = 0; kk < 8; kk++)
                LDSM4(pa[kk], sPs + afragP + kk * 32);
            #pragma unroll
            for (int dt = 0; dt < 8; dt++) {
                const uint32_t vb_ = sVs + bfragV + dt * (8 * ASTR * 4);
                uint32_t v0[4], v1[4], v2[4], v3[4];
                LDSM4(v0, vb_);
                LDSM4(v1, vb_ + 64);
                LDSM4(v2, vb_ + 128);
                LDSM4(v3, vb_ + 192);
                MMA_TF32(oacc[dt], pa[0], v0[0], v0[1]);
                MMA_TF32(oacc[dt], pa[1], v0[2], v0[3]);
                MMA_TF32(oacc[dt], pa[2], v1[0], v1[1]);
                MMA_TF32(oacc[dt], pa[3], v1[2], v1[3]);
                MMA_TF32(oacc[dt], pa[4], v2[0], v2[1]);
                MMA_TF32(oacc[dt], pa[5], v2[2], v2[3]);
                MMA_TF32(oacc[dt], pa[6], v3[0], v3[1]);
                MMA_TF32(oacc[dt], pa[7], v3[2], v3[3]);
            }
        }
        __syncthreads();
    }

    // epilogue: write fp32 o to [B,S,H*DK]
    #pragma unroll
    for (int half = 0; half < 2; half++) {
        const int sg = qc * 128 + w * 16 + g4 + half * 8;
        const float inv = 1.0f / lrow[half];
        const size_t base = (size_t)(b * NS + sg) * (NH * NDK) + h * NDK;
        #pragma unroll
        for (int dt = 0; dt < 8; dt++) {
            int d = dt * 8 + t4 * 2;
            float v0 = oacc[dt][half * 2]     * inv;
            float v1 = oacc[dt][half * 2 + 1] * inv;
            *(float2*)&o[base + d] = make_float2(v0, v1);
        }
    }
}

// ---------------- launcher ----------------------------------------------------
extern "C" void kernel_launch(void* const* d_in, const int* in_sizes, int n_in,
                              void* d_out, int out_size)
{
    const float* z   = (const float*)d_in[0];
    const float* r   = (const float*)d_in[1];
    const float* dwn = (const float*)d_in[2];
    const float* dbn = (const float*)d_in[3];
    const float* lng = (const float*)d_in[4];
    const float* lnb = (const float*)d_in[5];
    const float* wq  = (const float*)d_in[6];
    const float* bq  = (const float*)d_in[7];
    const float* wk  = (const float*)d_in[8];
    const float* bk  = (const float*)d_in[9];
    const float* wv  = (const float*)d_in[10];
    const float* bv  = (const float*)d_in[11];
    const float* wo  = (const float*)d_in[12];
    const float* bo  = (const float*)d_in[13];
    const float* dcw = (const float*)d_in[14];
    const float* dcb = (const float*)d_in[15];
    float* out = (float*)d_out;

    float *xcat, *x, *xn, *q, *k, *v, *o;
    float *wd, *wqr, *wkr, *wvr, *wc, *cadd;
    cudaGetSymbolAddress((void**)&xcat, g_xcat);
    cudaGetSymbolAddress((void**)&x,    g_x);
    cudaGetSymbolAddress((void**)&xn,   g_xn);
    cudaGetSymbolAddress((void**)&q,    g_q);
    cudaGetSymbolAddress((void**)&k,    g_k);
    cudaGetSymbolAddress((void**)&v,    g_v);
    cudaGetSymbolAddress((void**)&o,    g_o);
    cudaGetSymbolAddress((void**)&wd,   g_wd);
    cudaGetSymbolAddress((void**)&wqr,  g_wqr);
    cudaGetSymbolAddress((void**)&wkr,  g_wkr);
    cudaGetSymbolAddress((void**)&wvr,  g_wvr);
    cudaGetSymbolAddress((void**)&wc,   g_wc);
    cudaGetSymbolAddress((void**)&cadd, g_cadd);

    cudaFuncSetAttribute(gemm_tf32<0>, cudaFuncAttributeMaxDynamicSharedMemorySize, GEMM_SMEM);
    cudaFuncSetAttribute(gemm_tf32<1>, cudaFuncAttributeMaxDynamicSharedMemorySize, GEMM_SMEM);
    cudaFuncSetAttribute(attn_tc,      cudaFuncAttributeMaxDynamicSharedMemorySize, ATTN_SMEM);

    const int WELTS = FDEC * KP;
    concat_k<<<(MROWS * KP + 255) / 256, 256>>>(r, z, xcat);
    roundpad_k<<<(WELTS + 255) / 256, 256>>>(dwn, KINR, wd);
    roundpad_k<<<(WELTS + 255) / 256, 256>>>(wq, FDEC, wqr);
    roundpad_k<<<(WELTS + 255) / 256, 256>>>(wk, FDEC, wkr);
    roundpad_k<<<(WELTS + 255) / 256, 256>>>(wv, FDEC, wvr);
    wcomb_k<<<64, 256>>>(dcw, wo, wc);
    cvec_k<<<1, 512>>>(dcw, bo, dcb, cadd);

    dim3 ggrid(8, 64);
    gemm_tf32<0><<<ggrid, 256, GEMM_SMEM>>>(xcat, wd, dbn, x);
    ln_k<<<MROWS, 256>>>(x, lng, lnb, xn);
    gemm_tf32<1><<<ggrid, 256, GEMM_SMEM>>>(xn, wqr, bq, q);
    gemm_tf32<1><<<ggrid, 256, GEMM_SMEM>>>(xn, wkr, bk, k);
    gemm_tf32<1><<<ggrid, 256, GEMM_SMEM>>>(xn, wvr, bv, v);
    attn_tc<<<dim3(NS / 128, NH, NB), 256, ATTN_SMEM>>>(q, k, v, o);
    dec2_k<<<MROWS, 512>>>(x, o, dcw, wc, cadd, out);
}

// round 16
// speedup vs baseline: 1.0239x; 1.0239x over previous
#include <cuda_runtime.h>
#include <cuda_bf16.h>
#include <cstdint>
#include <math.h>

// Problem dims (fixed)
#define NB   8
#define NS   1024
#define NH   16
#define NDK  64
#define FDEC 1024
#define FD   16
#define KINR 784
#define KP   1024
#define MROWS (NB*NS)   // 8192

// ---------------- scratch (static __device__, no allocation) ----------------
__device__ float g_xcat[MROWS * KP];     // concat input, tf32-rounded
__device__ float g_x   [MROWS * FDEC];   // dense output (residual, fp32)
__device__ float g_xn  [MROWS * FDEC];   // LN output, tf32-rounded
__device__ float g_q   [MROWS * FDEC];   // tf32-rounded
__device__ float g_k   [MROWS * FDEC];   // tf32-rounded
__device__ float g_v   [MROWS * FDEC];   // tf32-rounded
__device__ float g_o   [MROWS * FDEC];   // attention out, fp32
__device__ float g_wd  [FDEC * KP];
__device__ float g_wqr [FDEC * KP];
__device__ float g_wkr [FDEC * KP];
__device__ float g_wvr [FDEC * KP];
__device__ float g_wc  [FD * FDEC];      // dcw @ wo
__device__ float g_cadd[FD];             // dcw . bo + dec_b

// ---------------- PTX helpers ------------------------------------------------
__device__ __forceinline__ uint32_t smem_u32(const void* p) {
    uint32_t a;
    asm("{ .reg .u64 t; cvta.to.shared.u64 t, %1; cvt.u32.u64 %0, t; }" : "=r"(a) : "l"(p));
    return a;
}

#define LDSM4(R, A) \
    asm volatile("ldmatrix.sync.aligned.m8n8.x4.shared.b16 {%0,%1,%2,%3}, [%4];" \
        : "=r"((R)[0]), "=r"((R)[1]), "=r"((R)[2]), "=r"((R)[3]) : "r"(A))

#define MMA_TF32(C, A, B0, B1) \
    asm volatile("mma.sync.aligned.m16n8k8.row.col.f32.tf32.tf32.f32 " \
        "{%0,%1,%2,%3},{%4,%5,%6,%7},{%8,%9},{%0,%1,%2,%3};" \
        : "+f"((C)[0]), "+f"((C)[1]), "+f"((C)[2]), "+f"((C)[3]) \
        : "r"((A)[0]), "r"((A)[1]), "r"((A)[2]), "r"((A)[3]), "r"(B0), "r"(B1))

__device__ __forceinline__ uint32_t to_tf32(float f) {
    uint32_t r;
    asm("cvt.rna.tf32.f32 %0, %1;" : "=r"(r) : "f"(f));
    return r;
}
__device__ __forceinline__ float tf32r(float f) {
    return __uint_as_float(to_tf32(f));
}
__device__ __forceinline__ float ex2(float x) {
    float r;
    asm("ex2.approx.f32 %0, %1;" : "=f"(r) : "f"(x));
    return r;
}

__device__ __forceinline__ void cpa16(uint32_t dst, const void* src) {
    asm volatile("cp.async.cg.shared.global [%0], [%1], 16;" :: "r"(dst), "l"(src));
}
#define CP_COMMIT() asm volatile("cp.async.commit_group;" ::: "memory")
#define CP_WAIT(n)  asm volatile("cp.async.wait_group %0;" :: "n"(n) : "memory")

#define LOG2E 1.4426950408889634f
#define QSC   (0.125f * LOG2E)

// ---------------- producers (tf32-rounded outputs) ---------------------------
__global__ void __launch_bounds__(256) concat_k(
    const float* __restrict__ r, const float* __restrict__ z,
    float* __restrict__ xcat)
{
    int idx = blockIdx.x * 256 + threadIdx.x;
    if (idx >= MROWS * KP) return;
    int m = idx >> 10, f = idx & 1023;
    float v = (f < 16) ? r[m * 16 + f]
            : (f < KINR) ? z[(m >> 10) * 768 + (f - 16)] : 0.f;
    xcat[idx] = tf32r(v);
}

__global__ void __launch_bounds__(256) roundpad_k(
    const float* __restrict__ w, int Ksrc, float* __restrict__ dst)
{
    int idx = blockIdx.x * 256 + threadIdx.x;
    if (idx >= FDEC * KP) return;
    int n = idx >> 10, k = idx & 1023;
    dst[idx] = (k < Ksrc) ? tf32r(w[n * Ksrc + k]) : 0.f;
}

// wc[n][c] = sum_j dcw[n][j] * wo[j][c]   (16 x 1024), exact fp32
__global__ void __launch_bounds__(256) wcomb_k(
    const float* __restrict__ dcw, const float* __restrict__ wo,
    float* __restrict__ wc)
{
    const int n = threadIdx.x >> 4;
    const int c = blockIdx.x * 16 + (threadIdx.x & 15);
    const float* dr = dcw + n * FDEC;
    float acc = 0.f;
    #pragma unroll 8
    for (int j = 0; j < FDEC; j++)
        acc += dr[j] * wo[(size_t)j * FDEC + c];
    wc[n * FDEC + c] = acc;
}

__global__ void __launch_bounds__(512) cvec_k(
    const float* __restrict__ dcw, const float* __restrict__ bo,
    const float* __restrict__ dcb, float* __restrict__ cadd)
{
    const int n = threadIdx.x >> 5, lane = threadIdx.x & 31;
    float sum = 0.f;
    #pragma unroll
    for (int i = 0; i < 8; i++) {
        float4 a = ((const float4*)(dcw + n * FDEC))[lane + i * 32];
        float4 b = ((const float4*)bo)[lane + i * 32];
        sum += a.x * b.x + a.y * b.y + a.z * b.z + a.w * b.w;
    }
    #pragma unroll
    for (int o = 16; o; o >>= 1) sum += __shfl_xor_sync(0xffffffffu, sum, o);
    if (lane == 0) cadd[n] = sum + dcb[n];
}

// ---------------- LayerNorm (fp32 in, tf32-rounded out) ----------------------
__device__ __forceinline__ float blockReduce(float val, float* sh)
{
    __syncthreads();
    int lane = threadIdx.x & 31, wid = threadIdx.x >> 5;
    #pragma unroll
    for (int o = 16; o; o >>= 1) val += __shfl_xor_sync(0xffffffffu, val, o);
    if (lane == 0) sh[wid] = val;
    __syncthreads();
    if (wid == 0) {
        val = (lane < 8) ? sh[lane] : 0.f;
        #pragma unroll
        for (int o = 4; o; o >>= 1) val += __shfl_xor_sync(0xffffffffu, val, o);
        if (lane == 0) sh[0] = val;
    }
    __syncthreads();
    return sh[0];
}

__global__ void __launch_bounds__(256) ln_k(
    const float* __restrict__ x, const float* __restrict__ g,
    const float* __restrict__ beta, float* __restrict__ xn)
{
    __shared__ float red[32];
    int row = blockIdx.x;
    float4 v = ((const float4*)(x + (size_t)row * 1024))[threadIdx.x];
    float s = blockReduce(v.x + v.y + v.z + v.w, red);
    float mean = s * (1.0f / 1024.0f);
    float dx = v.x - mean, dy = v.y - mean, dz = v.z - mean, dw = v.w - mean;
    float s2 = blockReduce(dx*dx + dy*dy + dz*dz + dw*dw, red);
    float inv = rsqrtf(s2 * (1.0f / 1024.0f) + 1e-6f);
    float4 gg = ((const float4*)g)[threadIdx.x];
    float4 bb = ((const float4*)beta)[threadIdx.x];
    float4 o;
    o.x = tf32r(gg.x * dx * inv + bb.x);
    o.y = tf32r(gg.y * dy * inv + bb.y);
    o.z = tf32r(gg.z * dz * inv + bb.z);
    o.w = tf32r(gg.w * dw * inv + bb.w);
    ((float4*)(xn + (size_t)row * 1024))[threadIdx.x] = o;
}

// ---------------- tf32 mma GEMM with ldmatrix fragments ----------------------
#define GSTR  36
#define TILE_BYTES (128 * GSTR * 4)
#define STAGE_B (2 * TILE_BYTES)
#define GEMM_SMEM (3 * STAGE_B)

template<int MODE>
__global__ void __launch_bounds__(256) gemm_tf32(
    const float* __restrict__ A, const float* __restrict__ Bw,
    const float* __restrict__ bias, float* __restrict__ C)
{
    extern __shared__ char sm[];
    const uint32_t sbase = smem_u32(sm);
    const int tid = threadIdx.x, lane = tid & 31, wid = tid >> 5;
    const int g4 = lane >> 2, t4 = lane & 3;
    const int bm = blockIdx.y * 128, bn = blockIdx.x * 128;
    const int wm = (wid & 3) * 32, wn = (wid >> 2) * 64;

    float acc[2][8][4];
    #pragma unroll
    for (int a = 0; a < 2; a++)
        #pragma unroll
        for (int b = 0; b < 8; b++)
            #pragma unroll
            for (int c = 0; c < 4; c++) acc[a][b][c] = 0.f;

    const uint32_t aoff =
        ((uint32_t)(wm + (lane & 7) + ((lane >> 3) & 1) * 8) * GSTR
         + ((lane >> 4) << 2)) * 4;
    const uint32_t boff =
        ((uint32_t)(wn + (lane & 7)) * GSTR + ((lane >> 3) & 3) * 4) * 4;

    auto load_stage = [&](int slot, int k0) {
        const uint32_t sa = sbase + slot * STAGE_B;
        #pragma unroll
        for (int c = 0; c < 4; c++) {
            int chunk = tid + c * 256;
            int row = chunk >> 3, seg = chunk & 7;
            cpa16(sa + row * (GSTR*4) + seg * 16,
                  A + (size_t)(bm + row) * KP + k0 + seg * 4);
        }
        const uint32_t sb = sa + TILE_BYTES;
        #pragma unroll
        for (int c = 0; c < 4; c++) {
            int chunk = tid + c * 256;
            int row = chunk >> 3, seg = chunk & 7;
            cpa16(sb + row * (GSTR*4) + seg * 16,
                  Bw + (size_t)(bn + row) * KP + k0 + seg * 4);
        }
    };

    load_stage(0, 0);  CP_COMMIT();
    load_stage(1, 32); CP_COMMIT();

    for (int i = 0; i < 32; i++) {
        if (i < 31) { CP_WAIT(1); } else { CP_WAIT(0); }
        __syncthreads();
        if (i + 2 < 32) { load_stage((i + 2) % 3, (i + 2) * 32); CP_COMMIT(); }

        const uint32_t As = sbase + (i % 3) * STAGE_B;
        const uint32_t Bs = As + TILE_BYTES;

        uint32_t a[4][2][4];
        #pragma unroll
        for (int kk = 0; kk < 4; kk++)
            #pragma unroll
            for (int am = 0; am < 2; am++)
                LDSM4(a[kk][am], As + aoff + am * (16 * GSTR * 4) + kk * 32);

        #pragma unroll
        for (int nt = 0; nt < 8; nt++) {
            uint32_t b01[4], b23[4];
            const uint32_t bb = Bs + boff + nt * (8 * GSTR * 4);
            LDSM4(b01, bb);
            LDSM4(b23, bb + 64);
            MMA_TF32(acc[0][nt], a[0][0], b01[0], b01[1]);
            MMA_TF32(acc[1][nt], a[0][1], b01[0], b01[1]);
            MMA_TF32(acc[0][nt], a[1][0], b01[2], b01[3]);
            MMA_TF32(acc[1][nt], a[1][1], b01[2], b01[3]);
            MMA_TF32(acc[0][nt], a[2][0], b23[0], b23[1]);
            MMA_TF32(acc[1][nt], a[2][1], b23[0], b23[1]);
            MMA_TF32(acc[0][nt], a[3][0], b23[2], b23[3]);
            MMA_TF32(acc[1][nt], a[3][1], b23[2], b23[3]);
        }
    }

    #pragma unroll
    for (int am = 0; am < 2; am++) {
        #pragma unroll
        for (int nt = 0; nt < 8; nt++) {
            int mrow = bm + wm + am * 16 + g4;
            int ncol = bn + wn + nt * 8 + t4 * 2;
            float b0 = bias[ncol], b1 = bias[ncol + 1];
            #pragma unroll
            for (int r = 0; r < 2; r++) {
                int m = mrow + r * 8;
                float v0 = acc[am][nt][r * 2]     + b0;
                float v1 = acc[am][nt][r * 2 + 1] + b1;
                if (MODE == 0) {
                    *(float2*)&C[(size_t)m * 1024 + ncol] = make_float2(v0, v1);
                } else {
                    int bb = m >> 10, s = m & 1023, h = ncol >> 6, d = ncol & 63;
                    *(float2*)&C[(size_t)(((bb << 4) + h) * 1024 + s) * 64 + d] =
                        make_float2(tf32r(v0), tf32r(v1));
                }
            }
        }
    }
}

// ---------------- fused decode: out = x.dw + o.wc + cadd, transposed ---------
__global__ void __launch_bounds__(512) dec2_k(
    const float* __restrict__ x, const float* __restrict__ o,
    const float* __restrict__ dw, const float* __restrict__ wc,
    const float* __restrict__ cadd, float* __restrict__ out)
{
    const int m = blockIdx.x;
    const int b = m >> 10, s = m & 1023;
    const int n = threadIdx.x >> 5;
    const int lane = threadIdx.x & 31;
    const float4* xr = (const float4*)(x  + (size_t)m * FDEC);
    const float4* orr = (const float4*)(o + (size_t)m * FDEC);
    const float4* wr = (const float4*)(dw + (size_t)n * FDEC);
    const float4* cr = (const float4*)(wc + (size_t)n * FDEC);
    float sum = 0.f;
    #pragma unroll
    for (int i = 0; i < 8; i++) {
        float4 a = xr[lane + i * 32];
        float4 w = wr[lane + i * 32];
        float4 oo = orr[lane + i * 32];
        float4 c = cr[lane + i * 32];
        sum += a.x * w.x + a.y * w.y + a.z * w.z + a.w * w.w;
        sum += oo.x * c.x + oo.y * c.y + oo.z * c.z + oo.w * c.w;
    }
    #pragma unroll
    for (int oo = 16; oo; oo >>= 1) sum += __shfl_xor_sync(0xffffffffu, sum, oo);
    if (lane == 0)
        out[(size_t)(b * FD + n) * NS + s] = sum + cadd[n];
}

// ---------------- tf32 mma flash attention, fixed-shift exp2 softmax ---------
// Scores computed in log2 domain (Q pre-scaled by 0.125*log2e). Per-row shift
// is the analytic ALiBi bound m_row = slope2*i (fixed, not a running max):
// all p ratios are exact; far-past weights underflow to 0 (<= 2^-120 of max).
// No max scan, no corr rescale, no oacc rescaling. ex2.approx handles the
// -1e9 causal mask (-> 0).
#define ASTR 68
#define ATTN_SMEM ((128 + 64 + 64 + 128) * ASTR * (int)sizeof(float))  // 104448

__global__ void __launch_bounds__(256) attn_tc(
    const float* __restrict__ q, const float* __restrict__ k,
    const float* __restrict__ v, float* __restrict__ o)
{
    extern __shared__ float smf[];
    float* Qs = smf;                   // [128][68] Q * 0.125*log2e (tf32)
    float* Ks = Qs + 128 * ASTR;       // [64][68]  K[j][d]
    float* Vs = Ks + 64 * ASTR;        // [64][68]  V^T
    float* Ps = Vs + 64 * ASTR;        // [128][68] P, tf32-rounded

    const int qc = blockIdx.x, h = blockIdx.y, b = blockIdx.z;
    const int tid = threadIdx.x, lane = tid & 31, w = tid >> 5;
    const int g4 = lane >> 2, t4 = lane & 3;

    const uint32_t sQs = smem_u32(Qs), sKs = smem_u32(Ks);
    const uint32_t sVs = smem_u32(Vs), sPs = smem_u32(Ps);

    const size_t head = (size_t)(b * NH + h) * NS * NDK;
    const float* qb = q + head;
    const float* kb = k + head;
    const float* vb = v + head;

    // load Q chunk (128 rows), scale into log2 domain, re-round to tf32
    {
        const int row = tid >> 1, col0 = (tid & 1) * 32;
        const float* src = qb + (size_t)(qc * 128 + row) * 64 + col0;
        float* dst = Qs + row * ASTR + col0;
        #pragma unroll
        for (int c = 0; c < 32; c += 4) {
            float4 t = *(const float4*)(src + c);
            t.x = tf32r(t.x * QSC); t.y = tf32r(t.y * QSC);
            t.z = tf32r(t.z * QSC); t.w = tf32r(t.w * QSC);
            *(float4*)(dst + c) = t;
        }
    }

    // fragment offsets
    const uint32_t bfrag = ((uint32_t)(lane & 7) * ASTR + ((lane >> 3) & 3) * 4) * 4;
    const uint32_t afrag =
        ((uint32_t)(w * 16 + (lane & 7) + ((lane >> 3) & 1) * 8) * ASTR
         + ((lane >> 4) << 2)) * 4;

    const float slope2 = exp2f(-0.5f * (float)(h + 1)) * LOG2E;
    float oacc[8][4];
    #pragma unroll
    for (int dt = 0; dt < 8; dt++)
        #pragma unroll
        for (int c = 0; c < 4; c++) oacc[dt][c] = 0.f;
    float lrow[2] = { 0.f, 0.f };

    const int lrow_ld = tid >> 2, lcol0 = (tid & 3) * 16;
    const int kmax = 2 * qc + 1;

    __syncthreads();   // Qs ready

    for (int kc = 0; kc <= kmax; kc++) {
        // load K [j][d]; V transposed [d][j]
        {
            const float* ksrc = kb + (size_t)(kc * 64 + lrow_ld) * 64 + lcol0;
            const float* vsrc = vb + (size_t)(kc * 64 + lrow_ld) * 64 + lcol0;
            float* kd = Ks + lrow_ld * ASTR + lcol0;
            #pragma unroll
            for (int c = 0; c < 16; c += 4) {
                float4 t = *(const float4*)(ksrc + c);
                *(float4*)(kd + c) = t;
                float4 tv = *(const float4*)(vsrc + c);
                Vs[(lcol0 + c + 0) * ASTR + lrow_ld] = tv.x;
                Vs[(lcol0 + c + 1) * ASTR + lrow_ld] = tv.y;
                Vs[(lcol0 + c + 2) * ASTR + lrow_ld] = tv.z;
                Vs[(lcol0 + c + 3) * ASTR + lrow_ld] = tv.w;
            }
        }
        __syncthreads();

        const bool active = !(kc == kmax && w < 4);
        if (active) {
            // Q a-fragments
            uint32_t qa[8][4];
            #pragma unroll
            for (int kk = 0; kk < 8; kk++)
                LDSM4(qa[kk], sQs + afrag + kk * 32);

            // S = Q K^T (log2 domain)
            float sc[8][4];
            #pragma unroll
            for (int nt = 0; nt < 8; nt++) {
                sc[nt][0] = sc[nt][1] = sc[nt][2] = sc[nt][3] = 0.f;
                const uint32_t kb_ = sKs + bfrag + nt * (8 * ASTR * 4);
                uint32_t b0[4], b1[4], b2[4], b3[4];
                LDSM4(b0, kb_);
                LDSM4(b1, kb_ + 64);
                LDSM4(b2, kb_ + 128);
                LDSM4(b3, kb_ + 192);
                MMA_TF32(sc[nt], qa[0], b0[0], b0[1]);
                MMA_TF32(sc[nt], qa[1], b0[2], b0[3]);
                MMA_TF32(sc[nt], qa[2], b1[0], b1[1]);
                MMA_TF32(sc[nt], qa[3], b1[2], b1[3]);
                MMA_TF32(sc[nt], qa[4], b2[0], b2[1]);
                MMA_TF32(sc[nt], qa[5], b2[2], b2[3]);
                MMA_TF32(sc[nt], qa[6], b3[0], b3[1]);
                MMA_TF32(sc[nt], qa[7], b3[2], b3[3]);
            }

            // fixed-shift softmax: x = sc + slope2*(jg - ig); p = 2^x
            const bool diag = (kc >= 2 * qc);
            #pragma unroll
            for (int half = 0; half < 2; half++) {
                const int wr = w * 16 + g4 + half * 8;
                const int ig = qc * 128 + wr;
                const float step = slope2 * 8.0f;
                float jnt0 = slope2 * (float)(kc * 64 + t4 * 2 - ig);
                float jnt1 = jnt0 + slope2;
                float rs = 0.f;
                #pragma unroll
                for (int nt = 0; nt < 8; nt++) {
                    float x0 = sc[nt][half * 2]     + jnt0;
                    float x1 = sc[nt][half * 2 + 1] + jnt1;
                    if (diag) {
                        int jg = kc * 64 + nt * 8 + t4 * 2;
                        if (jg > ig)     x0 = -1e9f;
                        if (jg + 1 > ig) x1 = -1e9f;
                    }
                    float p0 = ex2(x0);
                    float p1 = ex2(x1);
                    rs += p0 + p1;
                    *(float2*)&Ps[wr * ASTR + nt * 8 + t4 * 2] =
                        make_float2(tf32r(p0), tf32r(p1));
                    jnt0 += step; jnt1 += step;
                }
                rs += __shfl_xor_sync(0xffffffffu, rs, 1);
                rs += __shfl_xor_sync(0xffffffffu, rs, 2);
                lrow[half] += rs;
            }
            __syncwarp();

            // O += P V
            uint32_t pa[8][4];
            #pragma unroll
            for (int kk = 0; kk < 8; kk++)
                LDSM4(pa[kk], sPs + afrag + kk * 32);
            #pragma unroll
            for (int dt = 0; dt < 8; dt++) {
                const uint32_t vb_ = sVs + bfrag + dt * (8 * ASTR * 4);
                uint32_t v0[4], v1[4], v2[4], v3[4];
                LDSM4(v0, vb_);
                LDSM4(v1, vb_ + 64);
                LDSM4(v2, vb_ + 128);
                LDSM4(v3, vb_ + 192);
                MMA_TF32(oacc[dt], pa[0], v0[0], v0[1]);
                MMA_TF32(oacc[dt], pa[1], v0[2], v0[3]);
                MMA_TF32(oacc[dt], pa[2], v1[0], v1[1]);
                MMA_TF32(oacc[dt], pa[3], v1[2], v1[3]);
                MMA_TF32(oacc[dt], pa[4], v2[0], v2[1]);
                MMA_TF32(oacc[dt], pa[5], v2[2], v2[3]);
                MMA_TF32(oacc[dt], pa[6], v3[0], v3[1]);
                MMA_TF32(oacc[dt], pa[7], v3[2], v3[3]);
            }
        }
        __syncthreads();
    }

    // epilogue: write fp32 o to [B,S,H*DK]
    #pragma unroll
    for (int half = 0; half < 2; half++) {
        const int sg = qc * 128 + w * 16 + g4 + half * 8;
        const float inv = 1.0f / lrow[half];
        const size_t base = (size_t)(b * NS + sg) * (NH * NDK) + h * NDK;
        #pragma unroll
        for (int dt = 0; dt < 8; dt++) {
            int d = dt * 8 + t4 * 2;
            float v0 = oacc[dt][half * 2]     * inv;
            float v1 = oacc[dt][half * 2 + 1] * inv;
            *(float2*)&o[base + d] = make_float2(v0, v1);
        }
    }
}

// ---------------- launcher ----------------------------------------------------
extern "C" void kernel_launch(void* const* d_in, const int* in_sizes, int n_in,
                              void* d_out, int out_size)
{
    const float* z   = (const float*)d_in[0];
    const float* r   = (const float*)d_in[1];
    const float* dwn = (const float*)d_in[2];
    const float* dbn = (const float*)d_in[3];
    const float* lng = (const float*)d_in[4];
    const float* lnb = (const float*)d_in[5];
    const float* wq  = (const float*)d_in[6];
    const float* bq  = (const float*)d_in[7];
    const float* wk  = (const float*)d_in[8];
    const float* bk  = (const float*)d_in[9];
    const float* wv  = (const float*)d_in[10];
    const float* bv  = (const float*)d_in[11];
    const float* wo  = (const float*)d_in[12];
    const float* bo  = (const float*)d_in[13];
    const float* dcw = (const float*)d_in[14];
    const float* dcb = (const float*)d_in[15];
    float* out = (float*)d_out;

    float *xcat, *x, *xn, *q, *k, *v, *o;
    float *wd, *wqr, *wkr, *wvr, *wc, *cadd;
    cudaGetSymbolAddress((void**)&xcat, g_xcat);
    cudaGetSymbolAddress((void**)&x,    g_x);
    cudaGetSymbolAddress((void**)&xn,   g_xn);
    cudaGetSymbolAddress((void**)&q,    g_q);
    cudaGetSymbolAddress((void**)&k,    g_k);
    cudaGetSymbolAddress((void**)&v,    g_v);
    cudaGetSymbolAddress((void**)&o,    g_o);
    cudaGetSymbolAddress((void**)&wd,   g_wd);
    cudaGetSymbolAddress((void**)&wqr,  g_wqr);
    cudaGetSymbolAddress((void**)&wkr,  g_wkr);
    cudaGetSymbolAddress((void**)&wvr,  g_wvr);
    cudaGetSymbolAddress((void**)&wc,   g_wc);
    cudaGetSymbolAddress((void**)&cadd, g_cadd);

    cudaFuncSetAttribute(gemm_tf32<0>, cudaFuncAttributeMaxDynamicSharedMemorySize, GEMM_SMEM);
    cudaFuncSetAttribute(gemm_tf32<1>, cudaFuncAttributeMaxDynamicSharedMemorySize, GEMM_SMEM);
    cudaFuncSetAttribute(attn_tc,      cudaFuncAttributeMaxDynamicSharedMemorySize, ATTN_SMEM);

    const int WELTS = FDEC * KP;
    concat_k<<<(MROWS * KP + 255) / 256, 256>>>(r, z, xcat);
    roundpad_k<<<(WELTS + 255) / 256, 256>>>(dwn, KINR, wd);
    roundpad_k<<<(WELTS + 255) / 256, 256>>>(wq, FDEC, wqr);
    roundpad_k<<<(WELTS + 255) / 256, 256>>>(wk, FDEC, wkr);
    roundpad_k<<<(WELTS + 255) / 256, 256>>>(wv, FDEC, wvr);
    wcomb_k<<<64, 256>>>(dcw, wo, wc);
    cvec_k<<<1, 512>>>(dcw, bo, dcb, cadd);

    dim3 ggrid(8, 64);
    gemm_tf32<0><<<ggrid, 256, GEMM_SMEM>>>(xcat, wd, dbn, x);
    ln_k<<<MROWS, 256>>>(x, lng, lnb, xn);
    gemm_tf32<1><<<ggrid, 256, GEMM_SMEM>>>(xn, wqr, bq, q);
    gemm_tf32<1><<<ggrid, 256, GEMM_SMEM>>>(xn, wkr, bk, k);
    gemm_tf32<1><<<ggrid, 256, GEMM_SMEM>>>(xn, wvr, bv, v);
    attn_tc<<<dim3(NS / 128, NH, NB), 256, ATTN_SMEM>>>(q, k, v, o);
    dec2_k<<<MROWS, 512>>>(x, o, dcw, wc, cadd, out);
}

// round 17
// speedup vs baseline: 1.0240x; 1.0001x over previous
#include <cuda_runtime.h>
#include <cuda_bf16.h>
#include <cstdint>
#include <math.h>

// Problem dims (fixed)
#define NB   8
#define NS   1024
#define NH   16
#define NDK  64
#define FDEC 1024
#define FD   16
#define KINR 784
#define KP   1024
#define MROWS (NB*NS)   // 8192

// ---------------- scratch (static __device__, no allocation) ----------------
__device__ float g_xcat[MROWS * KP];     // concat input, tf32-rounded
__device__ float g_x   [MROWS * FDEC];   // dense output (residual, fp32)
__device__ float g_xn  [MROWS * FDEC];   // LN output, tf32-rounded
__device__ float g_q   [MROWS * FDEC];   // tf32-rounded
__device__ float g_k   [MROWS * FDEC];   // tf32-rounded
__device__ float g_v   [MROWS * FDEC];   // tf32-rounded
__device__ float g_o   [MROWS * FDEC];   // attention out, fp32
__device__ float g_wd  [FDEC * KP];
__device__ float g_wqr [FDEC * KP];
__device__ float g_wkr [FDEC * KP];
__device__ float g_wvr [FDEC * KP];
__device__ float g_wc  [FD * FDEC];      // dcw @ wo
__device__ float g_cadd[FD];             // dcw . bo + dec_b

// ---------------- PTX helpers ------------------------------------------------
__device__ __forceinline__ uint32_t smem_u32(const void* p) {
    uint32_t a;
    asm("{ .reg .u64 t; cvta.to.shared.u64 t, %1; cvt.u32.u64 %0, t; }" : "=r"(a) : "l"(p));
    return a;
}

#define LDSM4(R, A) \
    asm volatile("ldmatrix.sync.aligned.m8n8.x4.shared.b16 {%0,%1,%2,%3}, [%4];" \
        : "=r"((R)[0]), "=r"((R)[1]), "=r"((R)[2]), "=r"((R)[3]) : "r"(A))

#define MMA_TF32(C, A, B0, B1) \
    asm volatile("mma.sync.aligned.m16n8k8.row.col.f32.tf32.tf32.f32 " \
        "{%0,%1,%2,%3},{%4,%5,%6,%7},{%8,%9},{%0,%1,%2,%3};" \
        : "+f"((C)[0]), "+f"((C)[1]), "+f"((C)[2]), "+f"((C)[3]) \
        : "r"((A)[0]), "r"((A)[1]), "r"((A)[2]), "r"((A)[3]), "r"(B0), "r"(B1))

__device__ __forceinline__ uint32_t to_tf32(float f) {
    uint32_t r;
    asm("cvt.rna.tf32.f32 %0, %1;" : "=r"(r) : "f"(f));
    return r;
}
__device__ __forceinline__ float tf32r(float f) {
    return __uint_as_float(to_tf32(f));
}
__device__ __forceinline__ float ex2(float x) {
    float r;
    asm("ex2.approx.f32 %0, %1;" : "=f"(r) : "f"(x));
    return r;
}

__device__ __forceinline__ void cpa16(uint32_t dst, const void* src) {
    asm volatile("cp.async.cg.shared.global [%0], [%1], 16;" :: "r"(dst), "l"(src));
}
#define CP_COMMIT() asm volatile("cp.async.commit_group;" ::: "memory")
#define CP_WAIT(n)  asm volatile("cp.async.wait_group %0;" :: "n"(n) : "memory")

#define LOG2E 1.4426950408889634f
#define QSC   (0.125f * LOG2E)

// ---------------- producers (tf32-rounded outputs) ---------------------------
__global__ void __launch_bounds__(256) concat_k(
    const float* __restrict__ r, const float* __restrict__ z,
    float* __restrict__ xcat)
{
    int idx = blockIdx.x * 256 + threadIdx.x;
    if (idx >= MROWS * KP) return;
    int m = idx >> 10, f = idx & 1023;
    float v = (f < 16) ? r[m * 16 + f]
            : (f < KINR) ? z[(m >> 10) * 768 + (f - 16)] : 0.f;
    xcat[idx] = tf32r(v);
}

__global__ void __launch_bounds__(256) roundpad_k(
    const float* __restrict__ w, int Ksrc, float* __restrict__ dst)
{
    int idx = blockIdx.x * 256 + threadIdx.x;
    if (idx >= FDEC * KP) return;
    int n = idx >> 10, k = idx & 1023;
    dst[idx] = (k < Ksrc) ? tf32r(w[n * Ksrc + k]) : 0.f;
}

// wc[n][c] = sum_j dcw[n][j] * wo[j][c]   (16 x 1024), exact fp32
__global__ void __launch_bounds__(256) wcomb_k(
    const float* __restrict__ dcw, const float* __restrict__ wo,
    float* __restrict__ wc)
{
    const int n = threadIdx.x >> 4;
    const int c = blockIdx.x * 16 + (threadIdx.x & 15);
    const float* dr = dcw + n * FDEC;
    float acc = 0.f;
    #pragma unroll 8
    for (int j = 0; j < FDEC; j++)
        acc += dr[j] * wo[(size_t)j * FDEC + c];
    wc[n * FDEC + c] = acc;
}

__global__ void __launch_bounds__(512) cvec_k(
    const float* __restrict__ dcw, const float* __restrict__ bo,
    const float* __restrict__ dcb, float* __restrict__ cadd)
{
    const int n = threadIdx.x >> 5, lane = threadIdx.x & 31;
    float sum = 0.f;
    #pragma unroll
    for (int i = 0; i < 8; i++) {
        float4 a = ((const float4*)(dcw + n * FDEC))[lane + i * 32];
        float4 b = ((const float4*)bo)[lane + i * 32];
        sum += a.x * b.x + a.y * b.y + a.z * b.z + a.w * b.w;
    }
    #pragma unroll
    for (int o = 16; o; o >>= 1) sum += __shfl_xor_sync(0xffffffffu, sum, o);
    if (lane == 0) cadd[n] = sum + dcb[n];
}

// ---------------- LayerNorm (fp32 in, tf32-rounded out) ----------------------
__device__ __forceinline__ float blockReduce(float val, float* sh)
{
    __syncthreads();
    int lane = threadIdx.x & 31, wid = threadIdx.x >> 5;
    #pragma unroll
    for (int o = 16; o; o >>= 1) val += __shfl_xor_sync(0xffffffffu, val, o);
    if (lane == 0) sh[wid] = val;
    __syncthreads();
    if (wid == 0) {
        val = (lane < 8) ? sh[lane] : 0.f;
        #pragma unroll
        for (int o = 4; o; o >>= 1) val += __shfl_xor_sync(0xffffffffu, val, o);
        if (lane == 0) sh[0] = val;
    }
    __syncthreads();
    return sh[0];
}

__global__ void __launch_bounds__(256) ln_k(
    const float* __restrict__ x, const float* __restrict__ g,
    const float* __restrict__ beta, float* __restrict__ xn)
{
    __shared__ float red[32];
    int row = blockIdx.x;
    float4 v = ((const float4*)(x + (size_t)row * 1024))[threadIdx.x];
    float s = blockReduce(v.x + v.y + v.z + v.w, red);
    float mean = s * (1.0f / 1024.0f);
    float dx = v.x - mean, dy = v.y - mean, dz = v.z - mean, dw = v.w - mean;
    float s2 = blockReduce(dx*dx + dy*dy + dz*dz + dw*dw, red);
    float inv = rsqrtf(s2 * (1.0f / 1024.0f) + 1e-6f);
    float4 gg = ((const float4*)g)[threadIdx.x];
    float4 bb = ((const float4*)beta)[threadIdx.x];
    float4 o;
    o.x = tf32r(gg.x * dx * inv + bb.x);
    o.y = tf32r(gg.y * dy * inv + bb.y);
    o.z = tf32r(gg.z * dz * inv + bb.z);
    o.w = tf32r(gg.w * dw * inv + bb.w);
    ((float4*)(xn + (size_t)row * 1024))[threadIdx.x] = o;
}

// ---------------- tf32 mma GEMM with ldmatrix fragments ----------------------
#define GSTR  36
#define TILE_BYTES (128 * GSTR * 4)
#define STAGE_B (2 * TILE_BYTES)
#define GEMM_SMEM (3 * STAGE_B)

template<int MODE>
__global__ void __launch_bounds__(256) gemm_tf32(
    const float* __restrict__ A, const float* __restrict__ Bw,
    const float* __restrict__ bias, float* __restrict__ C)
{
    extern __shared__ char sm[];
    const uint32_t sbase = smem_u32(sm);
    const int tid = threadIdx.x, lane = tid & 31, wid = tid >> 5;
    const int g4 = lane >> 2, t4 = lane & 3;
    const int bm = blockIdx.y * 128, bn = blockIdx.x * 128;
    const int wm = (wid & 3) * 32, wn = (wid >> 2) * 64;

    float acc[2][8][4];
    #pragma unroll
    for (int a = 0; a < 2; a++)
        #pragma unroll
        for (int b = 0; b < 8; b++)
            #pragma unroll
            for (int c = 0; c < 4; c++) acc[a][b][c] = 0.f;

    const uint32_t aoff =
        ((uint32_t)(wm + (lane & 7) + ((lane >> 3) & 1) * 8) * GSTR
         + ((lane >> 4) << 2)) * 4;
    const uint32_t boff =
        ((uint32_t)(wn + (lane & 7)) * GSTR + ((lane >> 3) & 3) * 4) * 4;

    auto load_stage = [&](int slot, int k0) {
        const uint32_t sa = sbase + slot * STAGE_B;
        #pragma unroll
        for (int c = 0; c < 4; c++) {
            int chunk = tid + c * 256;
            int row = chunk >> 3, seg = chunk & 7;
            cpa16(sa + row * (GSTR*4) + seg * 16,
                  A + (size_t)(bm + row) * KP + k0 + seg * 4);
        }
        const uint32_t sb = sa + TILE_BYTES;
        #pragma unroll
        for (int c = 0; c < 4; c++) {
            int chunk = tid + c * 256;
            int row = chunk >> 3, seg = chunk & 7;
            cpa16(sb + row * (GSTR*4) + seg * 16,
                  Bw + (size_t)(bn + row) * KP + k0 + seg * 4);
        }
    };

    load_stage(0, 0);  CP_COMMIT();
    load_stage(1, 32); CP_COMMIT();

    for (int i = 0; i < 32; i++) {
        if (i < 31) { CP_WAIT(1); } else { CP_WAIT(0); }
        __syncthreads();
        if (i + 2 < 32) { load_stage((i + 2) % 3, (i + 2) * 32); CP_COMMIT(); }

        const uint32_t As = sbase + (i % 3) * STAGE_B;
        const uint32_t Bs = As + TILE_BYTES;

        uint32_t a[4][2][4];
        #pragma unroll
        for (int kk = 0; kk < 4; kk++)
            #pragma unroll
            for (int am = 0; am < 2; am++)
                LDSM4(a[kk][am], As + aoff + am * (16 * GSTR * 4) + kk * 32);

        #pragma unroll
        for (int nt = 0; nt < 8; nt++) {
            uint32_t b01[4], b23[4];
            const uint32_t bb = Bs + boff + nt * (8 * GSTR * 4);
            LDSM4(b01, bb);
            LDSM4(b23, bb + 64);
            MMA_TF32(acc[0][nt], a[0][0], b01[0], b01[1]);
            MMA_TF32(acc[1][nt], a[0][1], b01[0], b01[1]);
            MMA_TF32(acc[0][nt], a[1][0], b01[2], b01[3]);
            MMA_TF32(acc[1][nt], a[1][1], b01[2], b01[3]);
            MMA_TF32(acc[0][nt], a[2][0], b23[0], b23[1]);
            MMA_TF32(acc[1][nt], a[2][1], b23[0], b23[1]);
            MMA_TF32(acc[0][nt], a[3][0], b23[2], b23[3]);
            MMA_TF32(acc[1][nt], a[3][1], b23[2], b23[3]);
        }
    }

    #pragma unroll
    for (int am = 0; am < 2; am++) {
        #pragma unroll
        for (int nt = 0; nt < 8; nt++) {
            int mrow = bm + wm + am * 16 + g4;
            int ncol = bn + wn + nt * 8 + t4 * 2;
            float b0 = bias[ncol], b1 = bias[ncol + 1];
            #pragma unroll
            for (int r = 0; r < 2; r++) {
                int m = mrow + r * 8;
                float v0 = acc[am][nt][r * 2]     + b0;
                float v1 = acc[am][nt][r * 2 + 1] + b1;
                if (MODE == 0) {
                    *(float2*)&C[(size_t)m * 1024 + ncol] = make_float2(v0, v1);
                } else {
                    int bb = m >> 10, s = m & 1023, h = ncol >> 6, d = ncol & 63;
                    *(float2*)&C[(size_t)(((bb << 4) + h) * 1024 + s) * 64 + d] =
                        make_float2(tf32r(v0), tf32r(v1));
                }
            }
        }
    }
}

// ---------------- fused decode: out = x.dw + o.wc + cadd, transposed ---------
__global__ void __launch_bounds__(512) dec2_k(
    const float* __restrict__ x, const float* __restrict__ o,
    const float* __restrict__ dw, const float* __restrict__ wc,
    const float* __restrict__ cadd, float* __restrict__ out)
{
    const int m = blockIdx.x;
    const int b = m >> 10, s = m & 1023;
    const int n = threadIdx.x >> 5;
    const int lane = threadIdx.x & 31;
    const float4* xr = (const float4*)(x  + (size_t)m * FDEC);
    const float4* orr = (const float4*)(o + (size_t)m * FDEC);
    const float4* wr = (const float4*)(dw + (size_t)n * FDEC);
    const float4* cr = (const float4*)(wc + (size_t)n * FDEC);
    float sum = 0.f;
    #pragma unroll
    for (int i = 0; i < 8; i++) {
        float4 a = xr[lane + i * 32];
        float4 w = wr[lane + i * 32];
        float4 oo = orr[lane + i * 32];
        float4 c = cr[lane + i * 32];
        sum += a.x * w.x + a.y * w.y + a.z * w.z + a.w * w.w;
        sum += oo.x * c.x + oo.y * c.y + oo.z * c.z + oo.w * c.w;
    }
    #pragma unroll
    for (int oo = 16; oo; oo >>= 1) sum += __shfl_xor_sync(0xffffffffu, sum, oo);
    if (lane == 0)
        out[(size_t)(b * FD + n) * NS + s] = sum + cadd[n];
}

// ---------------- tf32 mma flash attention, pipelined + fused softmax --------
// Fixed-shift exp2 softmax (order-independent) fused into the S phase per nt.
// Next K/V tile prefetched into registers during compute (no extra smem).
#define ASTR 68
#define ATTN_SMEM ((128 + 64 + 64 + 128) * ASTR * (int)sizeof(float))  // 104448

__global__ void __launch_bounds__(256, 2) attn_tc(
    const float* __restrict__ q, const float* __restrict__ k,
    const float* __restrict__ v, float* __restrict__ o)
{
    extern __shared__ float smf[];
    float* Qs = smf;                   // [128][68] Q * 0.125*log2e (tf32)
    float* Ks = Qs + 128 * ASTR;       // [64][68]  K[j][d]
    float* Vs = Ks + 64 * ASTR;        // [64][68]  V^T
    float* Ps = Vs + 64 * ASTR;        // [128][68] P, tf32-rounded

    const int qc = blockIdx.x, h = blockIdx.y, b = blockIdx.z;
    const int tid = threadIdx.x, lane = tid & 31, w = tid >> 5;
    const int g4 = lane >> 2, t4 = lane & 3;

    const uint32_t sQs = smem_u32(Qs), sKs = smem_u32(Ks);
    const uint32_t sVs = smem_u32(Vs), sPs = smem_u32(Ps);

    const size_t head = (size_t)(b * NH + h) * NS * NDK;
    const float* qb = q + head;
    const float* kb = k + head;
    const float* vb = v + head;

    // load Q chunk (128 rows), scale into log2 domain, re-round to tf32
    {
        const int row = tid >> 1, col0 = (tid & 1) * 32;
        const float* src = qb + (size_t)(qc * 128 + row) * 64 + col0;
        float* dst = Qs + row * ASTR + col0;
        #pragma unroll
        for (int c = 0; c < 32; c += 4) {
            float4 t = *(const float4*)(src + c);
            t.x = tf32r(t.x * QSC); t.y = tf32r(t.y * QSC);
            t.z = tf32r(t.z * QSC); t.w = tf32r(t.w * QSC);
            *(float4*)(dst + c) = t;
        }
    }

    // fragment offsets
    const uint32_t bfrag = ((uint32_t)(lane & 7) * ASTR + ((lane >> 3) & 3) * 4) * 4;
    const uint32_t afrag =
        ((uint32_t)(w * 16 + (lane & 7) + ((lane >> 3) & 1) * 8) * ASTR
         + ((lane >> 4) << 2)) * 4;

    const float slope2 = exp2f(-0.5f * (float)(h + 1)) * LOG2E;
    float oacc[8][4];
    #pragma unroll
    for (int dt = 0; dt < 8; dt++)
        #pragma unroll
        for (int c = 0; c < 4; c++) oacc[dt][c] = 0.f;
    float lrow[2] = { 0.f, 0.f };

    const int lrow_ld = tid >> 2, lcol0 = (tid & 3) * 16;
    const int kmax = 2 * qc + 1;

    // prefetch tile 0 into registers
    float4 kf[4], vf[4];
    {
        const float* ksrc = kb + (size_t)lrow_ld * 64 + lcol0;
        const float* vsrc = vb + (size_t)lrow_ld * 64 + lcol0;
        #pragma unroll
        for (int c = 0; c < 4; c++) {
            kf[c] = *(const float4*)(ksrc + c * 4);
            vf[c] = *(const float4*)(vsrc + c * 4);
        }
    }

    __syncthreads();   // Qs ready

    for (int kc = 0; kc <= kmax; kc++) {
        // store staged K/V tile (K direct, V transposed)
        {
            float* kd = Ks + lrow_ld * ASTR + lcol0;
            #pragma unroll
            for (int c = 0; c < 4; c++) {
                *(float4*)(kd + c * 4) = kf[c];
                Vs[(lcol0 + c*4 + 0) * ASTR + lrow_ld] = vf[c].x;
                Vs[(lcol0 + c*4 + 1) * ASTR + lrow_ld] = vf[c].y;
                Vs[(lcol0 + c*4 + 2) * ASTR + lrow_ld] = vf[c].z;
                Vs[(lcol0 + c*4 + 3) * ASTR + lrow_ld] = vf[c].w;
            }
        }
        __syncthreads();

        // issue prefetch for next tile (overlaps with compute below)
        if (kc < kmax) {
            const float* ksrc = kb + (size_t)((kc + 1) * 64 + lrow_ld) * 64 + lcol0;
            const float* vsrc = vb + (size_t)((kc + 1) * 64 + lrow_ld) * 64 + lcol0;
            #pragma unroll
            for (int c = 0; c < 4; c++) {
                kf[c] = *(const float4*)(ksrc + c * 4);
                vf[c] = *(const float4*)(vsrc + c * 4);
            }
        }

        const bool active = !(kc == kmax && w < 4);
        if (active) {
            // Q a-fragments
            uint32_t qa[8][4];
            #pragma unroll
            for (int kk = 0; kk < 8; kk++)
                LDSM4(qa[kk], sQs + afrag + kk * 32);

            // fused S + softmax per nt
            const bool diag = (kc >= 2 * qc);
            const int wr0 = w * 16 + g4;
            const int ig0 = qc * 128 + wr0;
            const int ig1 = ig0 + 8;
            const float igs0 = slope2 * (float)ig0;
            const float igs1 = slope2 * (float)ig1;
            float j0 = slope2 * (float)(kc * 64 + t4 * 2);
            const float step = slope2 * 8.0f;
            float rs0 = 0.f, rs1 = 0.f;

            #pragma unroll
            for (int nt = 0; nt < 8; nt++) {
                float sc[4];
                sc[0] = sc[1] = sc[2] = sc[3] = 0.f;
                const uint32_t kb_ = sKs + bfrag + nt * (8 * ASTR * 4);
                uint32_t b0[4], b1[4], b2[4], b3[4];
                LDSM4(b0, kb_);
                LDSM4(b1, kb_ + 64);
                LDSM4(b2, kb_ + 128);
                LDSM4(b3, kb_ + 192);
                MMA_TF32(sc, qa[0], b0[0], b0[1]);
                MMA_TF32(sc, qa[1], b0[2], b0[3]);
                MMA_TF32(sc, qa[2], b1[0], b1[1]);
                MMA_TF32(sc, qa[3], b1[2], b1[3]);
                MMA_TF32(sc, qa[4], b2[0], b2[1]);
                MMA_TF32(sc, qa[5], b2[2], b2[3]);
                MMA_TF32(sc, qa[6], b3[0], b3[1]);
                MMA_TF32(sc, qa[7], b3[2], b3[3]);

                float x0 = sc[0] + (j0 - igs0);
                float x1 = sc[1] + (j0 + slope2 - igs0);
                float x2 = sc[2] + (j0 - igs1);
                float x3 = sc[3] + (j0 + slope2 - igs1);
                if (diag) {
                    int jg = kc * 64 + nt * 8 + t4 * 2;
                    if (jg > ig0)     x0 = -1e9f;
                    if (jg + 1 > ig0) x1 = -1e9f;
                    if (jg > ig1)     x2 = -1e9f;
                    if (jg + 1 > ig1) x3 = -1e9f;
                }
                float p0 = ex2(x0), p1 = ex2(x1);
                float p2 = ex2(x2), p3 = ex2(x3);
                rs0 += p0 + p1;
                rs1 += p2 + p3;
                *(float2*)&Ps[wr0 * ASTR + nt * 8 + t4 * 2] =
                    make_float2(tf32r(p0), tf32r(p1));
                *(float2*)&Ps[(wr0 + 8) * ASTR + nt * 8 + t4 * 2] =
                    make_float2(tf32r(p2), tf32r(p3));
                j0 += step;
            }
            rs0 += __shfl_xor_sync(0xffffffffu, rs0, 1);
            rs0 += __shfl_xor_sync(0xffffffffu, rs0, 2);
            rs1 += __shfl_xor_sync(0xffffffffu, rs1, 1);
            rs1 += __shfl_xor_sync(0xffffffffu, rs1, 2);
            lrow[0] += rs0;
            lrow[1] += rs1;
            __syncwarp();

            // O += P V
            uint32_t pa[8][4];
            #pragma unroll
            for (int kk = 0; kk < 8; kk++)
                LDSM4(pa[kk], sPs + afrag + kk * 32);
            #pragma unroll
            for (int dt = 0; dt < 8; dt++) {
                const uint32_t vb_ = sVs + bfrag + dt * (8 * ASTR * 4);
                uint32_t v0[4], v1[4], v2[4], v3[4];
                LDSM4(v0, vb_);
                LDSM4(v1, vb_ + 64);
                LDSM4(v2, vb_ + 128);
                LDSM4(v3, vb_ + 192);
                MMA_TF32(oacc[dt], pa[0], v0[0], v0[1]);
                MMA_TF32(oacc[dt], pa[1], v0[2], v0[3]);
                MMA_TF32(oacc[dt], pa[2], v1[0], v1[1]);
                MMA_TF32(oacc[dt], pa[3], v1[2], v1[3]);
                MMA_TF32(oacc[dt], pa[4], v2[0], v2[1]);
                MMA_TF32(oacc[dt], pa[5], v2[2], v2[3]);
                MMA_TF32(oacc[dt], pa[6], v3[0], v3[1]);
                MMA_TF32(oacc[dt], pa[7], v3[2], v3[3]);
            }
        }
        __syncthreads();
    }

    // epilogue: write fp32 o to [B,S,H*DK]
    #pragma unroll
    for (int half = 0; half < 2; half++) {
        const int sg = qc * 128 + w * 16 + g4 + half * 8;
        const float inv = 1.0f / lrow[half];
        const size_t base = (size_t)(b * NS + sg) * (NH * NDK) + h * NDK;
        #pragma unroll
        for (int dt = 0; dt < 8; dt++) {
            int d = dt * 8 + t4 * 2;
            float v0 = oacc[dt][half * 2]     * inv;
            float v1 = oacc[dt][half * 2 + 1] * inv;
            *(float2*)&o[base + d] = make_float2(v0, v1);
        }
    }
}

// ---------------- launcher ----------------------------------------------------
extern "C" void kernel_launch(void* const* d_in, const int* in_sizes, int n_in,
                              void* d_out, int out_size)
{
    const float* z   = (const float*)d_in[0];
    const float* r   = (const float*)d_in[1];
    const float* dwn = (const float*)d_in[2];
    const float* dbn = (const float*)d_in[3];
    const float* lng = (const float*)d_in[4];
    const float* lnb = (const float*)d_in[5];
    const float* wq  = (const float*)d_in[6];
    const float* bq  = (const float*)d_in[7];
    const float* wk  = (const float*)d_in[8];
    const float* bk  = (const float*)d_in[9];
    const float* wv  = (const float*)d_in[10];
    const float* bv  = (const float*)d_in[11];
    const float* wo  = (const float*)d_in[12];
    const float* bo  = (const float*)d_in[13];
    const float* dcw = (const float*)d_in[14];
    const float* dcb = (const float*)d_in[15];
    float* out = (float*)d_out;

    float *xcat, *x, *xn, *q, *k, *v, *o;
    float *wd, *wqr, *wkr, *wvr, *wc, *cadd;
    cudaGetSymbolAddress((void**)&xcat, g_xcat);
    cudaGetSymbolAddress((void**)&x,    g_x);
    cudaGetSymbolAddress((void**)&xn,   g_xn);
    cudaGetSymbolAddress((void**)&q,    g_q);
    cudaGetSymbolAddress((void**)&k,    g_k);
    cudaGetSymbolAddress((void**)&v,    g_v);
    cudaGetSymbolAddress((void**)&o,    g_o);
    cudaGetSymbolAddress((void**)&wd,   g_wd);
    cudaGetSymbolAddress((void**)&wqr,  g_wqr);
    cudaGetSymbolAddress((void**)&wkr,  g_wkr);
    cudaGetSymbolAddress((void**)&wvr,  g_wvr);
    cudaGetSymbolAddress((void**)&wc,   g_wc);
    cudaGetSymbolAddress((void**)&cadd, g_cadd);

    cudaFuncSetAttribute(gemm_tf32<0>, cudaFuncAttributeMaxDynamicSharedMemorySize, GEMM_SMEM);
    cudaFuncSetAttribute(gemm_tf32<1>, cudaFuncAttributeMaxDynamicSharedMemorySize, GEMM_SMEM);
    cudaFuncSetAttribute(attn_tc,      cudaFuncAttributeMaxDynamicSharedMemorySize, ATTN_SMEM);

    const int WELTS = FDEC * KP;
    concat_k<<<(MROWS * KP + 255) / 256, 256>>>(r, z, xcat);
    roundpad_k<<<(WELTS + 255) / 256, 256>>>(dwn, KINR, wd);
    roundpad_k<<<(WELTS + 255) / 256, 256>>>(wq, FDEC, wqr);
    roundpad_k<<<(WELTS + 255) / 256, 256>>>(wk, FDEC, wkr);
    roundpad_k<<<(WELTS + 255) / 256, 256>>>(wv, FDEC, wvr);
    wcomb_k<<<64, 256>>>(dcw, wo, wc);
    cvec_k<<<1, 512>>>(dcw, bo, dcb, cadd);

    dim3 ggrid(8, 64);
    gemm_tf32<0><<<ggrid, 256, GEMM_SMEM>>>(xcat, wd, dbn, x);
    ln_k<<<MROWS, 256>>>(x, lng, lnb, xn);
    gemm_tf32<1><<<ggrid, 256, GEMM_SMEM>>>(xn, wqr, bq, q);
    gemm_tf32<1><<<ggrid, 256, GEMM_SMEM>>>(xn, wkr, bk, k);
    gemm_tf32<1><<<ggrid, 256, GEMM_SMEM>>>(xn, wvr, bv, v);
    attn_tc<<<dim3(NS / 128, NH, NB), 256, ATTN_SMEM>>>(q, k, v, o);
    dec2_k<<<MROWS, 512>>>(x, o, dcw, wc, cadd, out);
}